// round 12
// baseline (speedup 1.0000x reference)
#include <cuda_runtime.h>
#include <math.h>

#define BB  512
#define TT  1024
#define TM  1023
#define FF  64
#define SN  128
#define HHD 128
#define G3  384
#define KC  192
#define HOR 24

typedef unsigned long long u64;

// ---------------- packed fp32 helpers (Blackwell f32x2 pipe) ----------------
__device__ __forceinline__ u64 pack2(float x, float y) {
    u64 r; asm("mov.b64 %0,{%1,%2};" : "=l"(r) : "f"(x), "f"(y)); return r;
}
__device__ __forceinline__ u64 splat2(float x) {
    u64 r; asm("mov.b64 %0,{%1,%1};" : "=l"(r) : "f"(x)); return r;
}
__device__ __forceinline__ float2 unpk2(u64 v) {
    float2 r; asm("mov.b64 {%0,%1},%2;" : "=f"(r.x), "=f"(r.y) : "l"(v)); return r;
}
__device__ __forceinline__ void fma2(u64& d, u64 a, u64 b) {
    asm("fma.rn.f32x2 %0,%1,%2,%0;" : "+l"(d) : "l"(a), "l"(b));
}

// ---------------- scratch (device globals; allocation-free) ----------------
__device__ float g_hs [(size_t)BB * TM * SN];   // h_s, overwritten in-place -> h_snn
__device__ float g_xp [(size_t)BB * TM * G3];   // x_proj
__device__ float g_gru[(size_t)BB * TM * HHD];  // gru_out
__device__ float g_sc [(size_t)BB * TM];        // attention scores

// ============================================================================
// K1: h_s[b,t,c] = sum_f (x[b,t+1,f]-x[b,t,f]) * proj_w[c,f] + proj_b[c]
// k-packed f32x2 accumulation.
// ============================================================================
__global__ __launch_bounds__(256) void k1_hs(const float* __restrict__ x,
                                             const float* __restrict__ pw,
                                             const float* __restrict__ pb) {
    __shared__ __align__(16) float wsh[FF * 129];   // [f*129 + c]
    __shared__ __align__(16) float dsh[32 * 68];    // [row*68 + f]
    int b   = blockIdx.y;
    int t0  = blockIdx.x * 32;
    int tid = threadIdx.x;

    for (int i = tid; i < SN * FF; i += 256) {
        int c = i >> 6, f = i & 63;
        wsh[f * 129 + c] = pw[i];
    }
    for (int i = tid; i < 32 * FF; i += 256) {
        int row = i >> 6, f = i & 63;
        int t = t0 + row;
        float d = 0.f;
        if (t < TM) {
            const float* xb = x + ((size_t)b * TT + t) * FF + f;
            d = xb[FF] - xb[0];
        }
        dsh[row * 68 + f] = d;
    }
    __syncthreads();

    int c  = tid & 127;
    int rg = tid >> 7;            // 0..1 -> 16 t's each
    u64 acc[16];
#pragma unroll
    for (int i = 0; i < 16; i++) acc[i] = 0ull;

#pragma unroll
    for (int f4 = 0; f4 < FF; f4 += 4) {
        u64 w01 = pack2(wsh[(f4 + 0) * 129 + c], wsh[(f4 + 1) * 129 + c]);
        u64 w23 = pack2(wsh[(f4 + 2) * 129 + c], wsh[(f4 + 3) * 129 + c]);
#pragma unroll
        for (int i = 0; i < 16; i++) {
            ulonglong2 d2 = *reinterpret_cast<const ulonglong2*>(&dsh[(rg * 16 + i) * 68 + f4]);
            fma2(acc[i], w01, d2.x);
            fma2(acc[i], w23, d2.y);
        }
    }
    float bias = pb[c];
#pragma unroll
    for (int i = 0; i < 16; i++) {
        int t = t0 + rg * 16 + i;
        float2 p = unpk2(acc[i]);
        if (t < TM) g_hs[((size_t)b * TM + t) * SN + c] = p.x + p.y + bias;
    }
}

// ============================================================================
// K2: LIF SNN scan, in-place on g_hs. One thread per (b, channel) chain.
// ============================================================================
__global__ __launch_bounds__(128) void k2_snn(const float* __restrict__ be1,
                                              const float* __restrict__ be2) {
    int c = threadIdx.x;
    int b = blockIdx.x;
    float bt1 = fminf(fmaxf(be1[c], 0.f), 0.99f);
    float bt2 = fminf(fmaxf(be2[c], 0.f), 0.99f);
    float m1 = 0.f, s1 = 0.f, m2 = 0.f, s2 = 0.f;
    float* p = g_hs + (size_t)b * TM * SN + c;

    int t = 0;
    for (; t + 4 <= TM; t += 4) {
        float i0 = p[0], i1 = p[SN], i2 = p[2 * SN], i3 = p[3 * SN];
        m1 = bt1 * m1 + i0 - s1; s1 = (m1 > 1.f) ? 1.f : 0.f;
        m2 = bt2 * m2 + s1 - s2; s2 = (m2 > 1.f) ? 1.f : 0.f;
        p[0] = m2;
        m1 = bt1 * m1 + i1 - s1; s1 = (m1 > 1.f) ? 1.f : 0.f;
        m2 = bt2 * m2 + s1 - s2; s2 = (m2 > 1.f) ? 1.f : 0.f;
        p[SN] = m2;
        m1 = bt1 * m1 + i2 - s1; s1 = (m1 > 1.f) ? 1.f : 0.f;
        m2 = bt2 * m2 + s1 - s2; s2 = (m2 > 1.f) ? 1.f : 0.f;
        p[2 * SN] = m2;
        m1 = bt1 * m1 + i3 - s1; s1 = (m1 > 1.f) ? 1.f : 0.f;
        m2 = bt2 * m2 + s1 - s2; s2 = (m2 > 1.f) ? 1.f : 0.f;
        p[3 * SN] = m2;
        p += 4 * SN;
    }
    for (; t < TM; t++) {
        float iv = p[0];
        m1 = bt1 * m1 + iv - s1; s1 = (m1 > 1.f) ? 1.f : 0.f;
        m2 = bt2 * m2 + s1 - s2; s2 = (m2 > 1.f) ? 1.f : 0.f;
        p[0] = m2;
        p += SN;
    }
}

// ============================================================================
// K3: x_proj = [raw | h_snn] @ W_ih^T + b_ih.  M=523776, N=384, K=192.
// 128x128 tile, BK=16, 8x8 microtile, f32x2 packed accumulation (pairs along i).
// ============================================================================
__global__ __launch_bounds__(256) void k3_xproj(const float* __restrict__ x,
                                                const float* __restrict__ wih,
                                                const float* __restrict__ bih) {
    __shared__ __align__(16) float As[16 * 132];
    __shared__ __align__(16) float Bs[16 * 132];
    int m0  = blockIdx.y * 128;
    int n0  = blockIdx.x * 128;
    int tid = threadIdx.x;
    int lr  = tid >> 1;     // 0..127: row (A) / col (B) for loads
    int lq  = tid & 1;      // k-half (8 floats each)

    int m  = m0 + lr;
    int b  = m / TM;
    int t  = m - b * TM;
    const float* xrow = x + ((size_t)b * TT + t + 1) * FF;   // raw, k < 64
    const float* hrow = g_hs + (size_t)m * SN;               // h_snn, k >= 64
    const float* brow = wih + (size_t)(n0 + lr) * KC;

    int ty = tid >> 4, tx = tid & 15;
    u64 acc[4][8];          // pairs along i: acc[p][j] = (row 2p, row 2p+1)
#pragma unroll
    for (int p = 0; p < 4; p++)
#pragma unroll
        for (int j = 0; j < 8; j++) acc[p][j] = 0ull;

    float4 a0, a1, bb0, bb1;
    {   // prologue load: ks = 0
        int k0 = lq * 8;
        a0  = *reinterpret_cast<const float4*>(xrow + k0);
        a1  = *reinterpret_cast<const float4*>(xrow + k0 + 4);
        bb0 = *reinterpret_cast<const float4*>(brow + k0);
        bb1 = *reinterpret_cast<const float4*>(brow + k0 + 4);
    }

    for (int ks = 0; ks < 12; ks++) {
        int kk = lq * 8;
        As[(kk + 0) * 132 + lr] = a0.x;  As[(kk + 1) * 132 + lr] = a0.y;
        As[(kk + 2) * 132 + lr] = a0.z;  As[(kk + 3) * 132 + lr] = a0.w;
        As[(kk + 4) * 132 + lr] = a1.x;  As[(kk + 5) * 132 + lr] = a1.y;
        As[(kk + 6) * 132 + lr] = a1.z;  As[(kk + 7) * 132 + lr] = a1.w;
        Bs[(kk + 0) * 132 + lr] = bb0.x; Bs[(kk + 1) * 132 + lr] = bb0.y;
        Bs[(kk + 2) * 132 + lr] = bb0.z; Bs[(kk + 3) * 132 + lr] = bb0.w;
        Bs[(kk + 4) * 132 + lr] = bb1.x; Bs[(kk + 5) * 132 + lr] = bb1.y;
        Bs[(kk + 6) * 132 + lr] = bb1.z; Bs[(kk + 7) * 132 + lr] = bb1.w;
        __syncthreads();

        if (ks < 11) {   // prefetch next k-tile (latency hidden by compute)
            int k0 = (ks + 1) * 16 + lq * 8;
            if (k0 < 64) {
                a0 = *reinterpret_cast<const float4*>(xrow + k0);
                a1 = *reinterpret_cast<const float4*>(xrow + k0 + 4);
            } else {
                a0 = *reinterpret_cast<const float4*>(hrow + k0 - 64);
                a1 = *reinterpret_cast<const float4*>(hrow + k0 - 60);
            }
            bb0 = *reinterpret_cast<const float4*>(brow + k0);
            bb1 = *reinterpret_cast<const float4*>(brow + k0 + 4);
        }

#pragma unroll
        for (int k2 = 0; k2 < 16; k2++) {
            ulonglong2 apl = *reinterpret_cast<const ulonglong2*>(&As[k2 * 132 + ty * 8]);
            ulonglong2 aph = *reinterpret_cast<const ulonglong2*>(&As[k2 * 132 + ty * 8 + 4]);
            float4 bv0 = *reinterpret_cast<const float4*>(&Bs[k2 * 132 + tx * 8]);
            float4 bv1 = *reinterpret_cast<const float4*>(&Bs[k2 * 132 + tx * 8 + 4]);
            u64 ap[4] = {apl.x, apl.y, aph.x, aph.y};
            u64 bs[8];
            bs[0] = splat2(bv0.x); bs[1] = splat2(bv0.y);
            bs[2] = splat2(bv0.z); bs[3] = splat2(bv0.w);
            bs[4] = splat2(bv1.x); bs[5] = splat2(bv1.y);
            bs[6] = splat2(bv1.z); bs[7] = splat2(bv1.w);
#pragma unroll
            for (int p = 0; p < 4; p++)
#pragma unroll
                for (int j = 0; j < 8; j++) fma2(acc[p][j], ap[p], bs[j]);
        }
        __syncthreads();
    }

    float bias[8];
#pragma unroll
    for (int j = 0; j < 8; j++) bias[j] = bih[n0 + tx * 8 + j];
#pragma unroll
    for (int p = 0; p < 4; p++) {
        float* orow0 = g_xp + (size_t)(m0 + ty * 8 + 2 * p) * G3 + n0 + tx * 8;
        float* orow1 = orow0 + G3;
#pragma unroll
        for (int j = 0; j < 8; j++) {
            float2 v = unpk2(acc[p][j]);
            orow0[j] = v.x + bias[j];
            orow1[j] = v.y + bias[j];
        }
    }
}

// ============================================================================
// K4: GRU scan. Persistent: 128 CTAs x 4 batch rows. 768 threads =
// 384 outputs x 2 k-halves; W_hh register-resident; f32x2 packed dot products;
// 2 barriers/step (halves write disjoint partial buffers).
// ============================================================================
__global__ __launch_bounds__(768, 1) void k4_gru(const float* __restrict__ whh,
                                                 const float* __restrict__ bhh) {
    __shared__ __align__(16) float hsh[4][HHD];
    __shared__ float gh0[4][G3];
    __shared__ float gh1[4][G3];
    __shared__ float xpsh[2][4][G3];

    int tid  = threadIdx.x;
    int half = (tid >= 384) ? 1 : 0;
    int j    = tid - half * 384;
    int b0   = blockIdx.x * 4;

    ulonglong2 w2[16];      // 64 w-floats packed as f32x2 pairs along k
    const ulonglong2* wp =
        reinterpret_cast<const ulonglong2*>(whh + (size_t)j * HHD + half * 64);
#pragma unroll
    for (int i = 0; i < 16; i++) w2[i] = wp[i];
    float bj = bhh[j];

    for (int i = tid; i < 4 * HHD; i += 768) hsh[i >> 7][i & 127] = 0.f;
    // preload xp for t = 0
    xpsh[0][half][j]     = g_xp[((size_t)(b0 + half) * TM) * G3 + j];
    xpsh[0][2 + half][j] = g_xp[((size_t)(b0 + 2 + half) * TM) * G3 + j];
    __syncthreads();

    const float* pfA = g_xp + ((size_t)(b0 + half) * TM + 1) * G3 + j;
    const float* pfB = g_xp + ((size_t)(b0 + 2 + half) * TM + 1) * G3 + j;

    int r0 = tid >> 7;       // update-phase mapping (tid < 512)
    int cc = tid & 127;
    float* gout = g_gru + ((size_t)(b0 + r0) * TM) * HHD + cc;

    for (int t = 0; t < TM; t++) {
        int cur = t & 1, nb = cur ^ 1;

        float pf0 = 0.f, pf1 = 0.f;
        if (t + 1 < TM) { pf0 = *pfA; pf1 = *pfB; }
        pfA += G3; pfB += G3;

        u64 a0 = 0ull, a1 = 0ull, a2 = 0ull, a3 = 0ull;
        const ulonglong2* h0 = reinterpret_cast<const ulonglong2*>(&hsh[0][half * 64]);
        const ulonglong2* h1 = reinterpret_cast<const ulonglong2*>(&hsh[1][half * 64]);
        const ulonglong2* h2 = reinterpret_cast<const ulonglong2*>(&hsh[2][half * 64]);
        const ulonglong2* h3 = reinterpret_cast<const ulonglong2*>(&hsh[3][half * 64]);
#pragma unroll
        for (int kq = 0; kq < 16; kq++) {
            ulonglong2 w = w2[kq];
            ulonglong2 v0 = h0[kq];
            fma2(a0, w.x, v0.x); fma2(a0, w.y, v0.y);
            ulonglong2 v1 = h1[kq];
            fma2(a1, w.x, v1.x); fma2(a1, w.y, v1.y);
            ulonglong2 v2 = h2[kq];
            fma2(a2, w.x, v2.x); fma2(a2, w.y, v2.y);
            ulonglong2 v3 = h3[kq];
            fma2(a3, w.x, v3.x); fma2(a3, w.y, v3.y);
        }
        float2 p0 = unpk2(a0), p1 = unpk2(a1), p2 = unpk2(a2), p3 = unpk2(a3);

        xpsh[nb][half][j]     = pf0;     // stash prefetch (read next step)
        xpsh[nb][2 + half][j] = pf1;
        if (half) {
            gh1[0][j] = p0.x + p0.y;
            gh1[1][j] = p1.x + p1.y;
            gh1[2][j] = p2.x + p2.y;
            gh1[3][j] = p3.x + p3.y;
        } else {
            gh0[0][j] = p0.x + p0.y + bj;
            gh0[1][j] = p1.x + p1.y + bj;
            gh0[2][j] = p2.x + p2.y + bj;
            gh0[3][j] = p3.x + p3.y + bj;
        }
        __syncthreads();

        if (tid < 512) {
            float xr = xpsh[cur][r0][cc];
            float xz = xpsh[cur][r0][cc + 128];
            float xn = xpsh[cur][r0][cc + 256];
            float hr = gh0[r0][cc]       + gh1[r0][cc];
            float hz = gh0[r0][cc + 128] + gh1[r0][cc + 128];
            float hn = gh0[r0][cc + 256] + gh1[r0][cc + 256];
            float rr = 1.f / (1.f + __expf(-(xr + hr)));
            float zg = 1.f / (1.f + __expf(-(xz + hz)));
            float nn = tanhf(xn + rr * hn);
            float hnew = (1.f - zg) * nn + zg * hsh[r0][cc];
            hsh[r0][cc] = hnew;
            *gout = hnew;
        }
        gout += HHD;
        __syncthreads();
    }
}

// ============================================================================
// K5: scores = relu(gru @ w1^T + b1) @ w2^T + b2.  Block: one b x 64 t's.
// f32x2 packed along k.
// ============================================================================
__global__ __launch_bounds__(256) void k5_scores(const float* __restrict__ w1,
                                                 const float* __restrict__ ab1,
                                                 const float* __restrict__ w2,
                                                 const float* __restrict__ ab2) {
    __shared__ __align__(16) float gsh[64 * 132];   // gru tile [tl*132 + k]
    __shared__ float wred[8][16];                   // per-warp partial scores
    int b   = blockIdx.y;
    int t0  = blockIdx.x * 64;
    int tid = threadIdx.x;

    for (int i = tid; i < 64 * 128; i += 256) {
        int tl = i >> 7, k = i & 127;
        int t = t0 + tl;
        gsh[tl * 132 + k] = (t < TM) ? g_gru[((size_t)b * TM + t) * HHD + k] : 0.f;
    }
    __syncthreads();

    int n  = tid & 63;
    int tg = tid >> 6;                  // 4 groups x 16 t's
    float bn  = ab1[n];
    float w2n = w2[n];

    u64 hid[16];
#pragma unroll
    for (int i = 0; i < 16; i++) hid[i] = 0ull;

    const float* wrow = w1 + (size_t)n * HHD;
#pragma unroll 8
    for (int k4 = 0; k4 < 32; k4++) {
        ulonglong2 wv = *reinterpret_cast<const ulonglong2*>(wrow + k4 * 4);
#pragma unroll
        for (int i = 0; i < 16; i++) {
            ulonglong2 gv =
                *reinterpret_cast<const ulonglong2*>(&gsh[(tg * 16 + i) * 132 + k4 * 4]);
            fma2(hid[i], wv.x, gv.x);
            fma2(hid[i], wv.y, gv.y);
        }
    }

    // per-thread contribution, warp-reduce over the 32 n-lanes of this warp
    int wid = tid >> 5;
#pragma unroll
    for (int i = 0; i < 16; i++) {
        float2 hp = unpk2(hid[i]);
        float sv = fmaxf(hp.x + hp.y + bn, 0.f) * w2n;
#pragma unroll
        for (int o = 16; o; o >>= 1) sv += __shfl_xor_sync(0xffffffffu, sv, o);
        if ((tid & 31) == 0) wred[wid][i] = sv;
    }
    __syncthreads();

    if (tid < 64) {                      // t_local = tid; warps 2*tg, 2*tg+1
        int tgg = tid >> 4, ii = tid & 15;
        float s = wred[2 * tgg][ii] + wred[2 * tgg + 1][ii] + ab2[0];
        int t = t0 + tid;
        if (t < TM) g_sc[(size_t)b * TM + t] = s;
    }
}

// ============================================================================
// K6: softmax over t, weighted pool of gru_out, fused head. One block per b.
// ============================================================================
__global__ __launch_bounds__(128) void k6_pool(const float* __restrict__ hw,
                                               const float* __restrict__ hb,
                                               float* __restrict__ out) {
    __shared__ float psh[TM];
    __shared__ float red[16];
    __shared__ float hann[HHD];
    int b   = blockIdx.x;
    int tid = threadIdx.x;
    const float* sc = g_sc + (size_t)b * TM;

    float mx = -1e30f;
    for (int t = tid; t < TM; t += 128) mx = fmaxf(mx, sc[t]);
#pragma unroll
    for (int o = 16; o; o >>= 1) mx = fmaxf(mx, __shfl_xor_sync(0xffffffffu, mx, o));
    if ((tid & 31) == 0) red[tid >> 5] = mx;
    __syncthreads();
    mx = fmaxf(fmaxf(red[0], red[1]), fmaxf(red[2], red[3]));

    float sm = 0.f;
    for (int t = tid; t < TM; t += 128) {
        float e = __expf(sc[t] - mx);
        psh[t] = e;
        sm += e;
    }
#pragma unroll
    for (int o = 16; o; o >>= 1) sm += __shfl_xor_sync(0xffffffffu, sm, o);
    if ((tid & 31) == 0) red[8 + (tid >> 5)] = sm;
    __syncthreads();
    sm = red[8] + red[9] + red[10] + red[11];
    float inv = 1.f / sm;

    const float* gb = g_gru + (size_t)b * TM * HHD + tid;   // tid == channel
    float acc = 0.f;
    int t = 0;
    for (; t + 4 <= TM; t += 4) {
        float g0 = gb[(size_t)(t + 0) * HHD];
        float g1 = gb[(size_t)(t + 1) * HHD];
        float g2 = gb[(size_t)(t + 2) * HHD];
        float g3 = gb[(size_t)(t + 3) * HHD];
        acc += psh[t] * g0 + psh[t + 1] * g1 + psh[t + 2] * g2 + psh[t + 3] * g3;
    }
    for (; t < TM; t++) acc += psh[t] * gb[(size_t)t * HHD];
    hann[tid] = acc * inv;
    __syncthreads();

    if (tid < HOR) {
        float s = hb[tid];
        const float* wr = hw + tid * HHD;
#pragma unroll 4
        for (int c = 0; c < HHD; c++) s += hann[c] * wr[c];
        out[b * HOR + tid] = s;
    }
}

// ============================================================================
extern "C" void kernel_launch(void* const* d_in, const int* in_sizes, int n_in,
                              void* d_out, int out_size) {
    const float* x       = (const float*)d_in[0];
    const float* proj_w  = (const float*)d_in[1];
    const float* proj_b  = (const float*)d_in[2];
    const float* beta1   = (const float*)d_in[3];
    const float* beta2   = (const float*)d_in[4];
    const float* gw_ih   = (const float*)d_in[5];
    const float* gw_hh   = (const float*)d_in[6];
    const float* gb_ih   = (const float*)d_in[7];
    const float* gb_hh   = (const float*)d_in[8];
    const float* attn_w1 = (const float*)d_in[9];
    const float* attn_b1 = (const float*)d_in[10];
    const float* attn_w2 = (const float*)d_in[11];
    const float* attn_b2 = (const float*)d_in[12];
    const float* head_w  = (const float*)d_in[13];
    const float* head_b  = (const float*)d_in[14];
    float* out = (float*)d_out;

    dim3 g1(32, BB);
    k1_hs<<<g1, 256>>>(x, proj_w, proj_b);
    k2_snn<<<BB, 128>>>(beta1, beta2);
    dim3 g3(3, 4092);                       // 384/128 n-tiles x 523776/128 m-tiles
    k3_xproj<<<g3, 256>>>(x, gw_ih, gb_ih);
    k4_gru<<<128, 768>>>(gw_hh, gb_hh);
    dim3 g5(16, BB);                        // ceil(1023/64) t-tiles x B
    k5_scores<<<g5, 256>>>(attn_w1, attn_b1, attn_w2, attn_b2);
    k6_pool<<<BB, 128>>>(head_w, head_b, out);
}

// round 15
// speedup vs baseline: 1.0032x; 1.0032x over previous
#include <cuda_runtime.h>
#include <math.h>

#define BB  512
#define TT  1024
#define TM  1023
#define FF  64
#define SN  128
#define HHD 128
#define G3  384
#define KC  192
#define HOR 24

typedef unsigned long long u64;

// ---------------- packed fp32 helpers (Blackwell f32x2 pipe) ----------------
__device__ __forceinline__ u64 pack2(float x, float y) {
    u64 r; asm("mov.b64 %0,{%1,%2};" : "=l"(r) : "f"(x), "f"(y)); return r;
}
__device__ __forceinline__ u64 splat2(float x) {
    u64 r; asm("mov.b64 %0,{%1,%1};" : "=l"(r) : "f"(x)); return r;
}
__device__ __forceinline__ float2 unpk2(u64 v) {
    float2 r; asm("mov.b64 {%0,%1},%2;" : "=f"(r.x), "=f"(r.y) : "l"(v)); return r;
}
__device__ __forceinline__ void fma2(u64& d, u64 a, u64 b) {
    asm("fma.rn.f32x2 %0,%1,%2,%0;" : "+l"(d) : "l"(a), "l"(b));
}

// ---------------- scratch (device globals; allocation-free) ----------------
__device__ float g_hs [(size_t)BB * TM * SN];   // h_s, overwritten in-place -> h_snn
__device__ float g_xp [(size_t)BB * TM * G3];   // x_proj
__device__ float g_gru[(size_t)BB * TM * HHD];  // gru_out
__device__ float g_sc [(size_t)BB * TM];        // attention scores

// ============================================================================
// K1: h_s[b,t,c] = sum_f (x[b,t+1,f]-x[b,t,f]) * proj_w[c,f] + proj_b[c]
// k-packed f32x2 accumulation.
// ============================================================================
__global__ __launch_bounds__(256) void k1_hs(const float* __restrict__ x,
                                             const float* __restrict__ pw,
                                             const float* __restrict__ pb) {
    __shared__ __align__(16) float wsh[FF * 129];   // [f*129 + c]
    __shared__ __align__(16) float dsh[32 * 68];    // [row*68 + f]
    int b   = blockIdx.y;
    int t0  = blockIdx.x * 32;
    int tid = threadIdx.x;

    for (int i = tid; i < SN * FF; i += 256) {
        int c = i >> 6, f = i & 63;
        wsh[f * 129 + c] = pw[i];
    }
    for (int i = tid; i < 32 * FF; i += 256) {
        int row = i >> 6, f = i & 63;
        int t = t0 + row;
        float d = 0.f;
        if (t < TM) {
            const float* xb = x + ((size_t)b * TT + t) * FF + f;
            d = xb[FF] - xb[0];
        }
        dsh[row * 68 + f] = d;
    }
    __syncthreads();

    int c  = tid & 127;
    int rg = tid >> 7;            // 0..1 -> 16 t's each
    u64 acc[16];
#pragma unroll
    for (int i = 0; i < 16; i++) acc[i] = 0ull;

#pragma unroll
    for (int f4 = 0; f4 < FF; f4 += 4) {
        u64 w01 = pack2(wsh[(f4 + 0) * 129 + c], wsh[(f4 + 1) * 129 + c]);
        u64 w23 = pack2(wsh[(f4 + 2) * 129 + c], wsh[(f4 + 3) * 129 + c]);
#pragma unroll
        for (int i = 0; i < 16; i++) {
            ulonglong2 d2 = *reinterpret_cast<const ulonglong2*>(&dsh[(rg * 16 + i) * 68 + f4]);
            fma2(acc[i], w01, d2.x);
            fma2(acc[i], w23, d2.y);
        }
    }
    float bias = pb[c];
#pragma unroll
    for (int i = 0; i < 16; i++) {
        int t = t0 + rg * 16 + i;
        float2 p = unpk2(acc[i]);
        if (t < TM) g_hs[((size_t)b * TM + t) * SN + c] = p.x + p.y + bias;
    }
}

// ============================================================================
// K2: LIF SNN scan, in-place on g_hs. One thread per (b, channel) chain.
// ============================================================================
__global__ __launch_bounds__(128) void k2_snn(const float* __restrict__ be1,
                                              const float* __restrict__ be2) {
    int c = threadIdx.x;
    int b = blockIdx.x;
    float bt1 = fminf(fmaxf(be1[c], 0.f), 0.99f);
    float bt2 = fminf(fmaxf(be2[c], 0.f), 0.99f);
    float m1 = 0.f, s1 = 0.f, m2 = 0.f, s2 = 0.f;
    float* p = g_hs + (size_t)b * TM * SN + c;

    int t = 0;
    for (; t + 4 <= TM; t += 4) {
        float i0 = p[0], i1 = p[SN], i2 = p[2 * SN], i3 = p[3 * SN];
        m1 = bt1 * m1 + i0 - s1; s1 = (m1 > 1.f) ? 1.f : 0.f;
        m2 = bt2 * m2 + s1 - s2; s2 = (m2 > 1.f) ? 1.f : 0.f;
        p[0] = m2;
        m1 = bt1 * m1 + i1 - s1; s1 = (m1 > 1.f) ? 1.f : 0.f;
        m2 = bt2 * m2 + s1 - s2; s2 = (m2 > 1.f) ? 1.f : 0.f;
        p[SN] = m2;
        m1 = bt1 * m1 + i2 - s1; s1 = (m1 > 1.f) ? 1.f : 0.f;
        m2 = bt2 * m2 + s1 - s2; s2 = (m2 > 1.f) ? 1.f : 0.f;
        p[2 * SN] = m2;
        m1 = bt1 * m1 + i3 - s1; s1 = (m1 > 1.f) ? 1.f : 0.f;
        m2 = bt2 * m2 + s1 - s2; s2 = (m2 > 1.f) ? 1.f : 0.f;
        p[3 * SN] = m2;
        p += 4 * SN;
    }
    for (; t < TM; t++) {
        float iv = p[0];
        m1 = bt1 * m1 + iv - s1; s1 = (m1 > 1.f) ? 1.f : 0.f;
        m2 = bt2 * m2 + s1 - s2; s2 = (m2 > 1.f) ? 1.f : 0.f;
        p[0] = m2;
        p += SN;
    }
}

// ============================================================================
// K3: x_proj = [raw | h_snn] @ W_ih^T + b_ih.  M=523776, N=384, K=192.
// 128x128 tile, BK=16, 8x8 microtile, f32x2 packed accumulation (pairs along i).
// ============================================================================
__global__ __launch_bounds__(256) void k3_xproj(const float* __restrict__ x,
                                                const float* __restrict__ wih,
                                                const float* __restrict__ bih) {
    __shared__ __align__(16) float As[16 * 132];
    __shared__ __align__(16) float Bs[16 * 132];
    int m0  = blockIdx.y * 128;
    int n0  = blockIdx.x * 128;
    int tid = threadIdx.x;
    int lr  = tid >> 1;     // 0..127: row (A) / col (B) for loads
    int lq  = tid & 1;      // k-half (8 floats each)

    int m  = m0 + lr;
    int b  = m / TM;
    int t  = m - b * TM;
    const float* xrow = x + ((size_t)b * TT + t + 1) * FF;   // raw, k < 64
    const float* hrow = g_hs + (size_t)m * SN;               // h_snn, k >= 64
    const float* brow = wih + (size_t)(n0 + lr) * KC;

    int ty = tid >> 4, tx = tid & 15;
    u64 acc[4][8];          // pairs along i: acc[p][j] = (row 2p, row 2p+1)
#pragma unroll
    for (int p = 0; p < 4; p++)
#pragma unroll
        for (int j = 0; j < 8; j++) acc[p][j] = 0ull;

    float4 a0, a1, bb0, bb1;
    {   // prologue load: ks = 0
        int k0 = lq * 8;
        a0  = *reinterpret_cast<const float4*>(xrow + k0);
        a1  = *reinterpret_cast<const float4*>(xrow + k0 + 4);
        bb0 = *reinterpret_cast<const float4*>(brow + k0);
        bb1 = *reinterpret_cast<const float4*>(brow + k0 + 4);
    }

    for (int ks = 0; ks < 12; ks++) {
        int kk = lq * 8;
        As[(kk + 0) * 132 + lr] = a0.x;  As[(kk + 1) * 132 + lr] = a0.y;
        As[(kk + 2) * 132 + lr] = a0.z;  As[(kk + 3) * 132 + lr] = a0.w;
        As[(kk + 4) * 132 + lr] = a1.x;  As[(kk + 5) * 132 + lr] = a1.y;
        As[(kk + 6) * 132 + lr] = a1.z;  As[(kk + 7) * 132 + lr] = a1.w;
        Bs[(kk + 0) * 132 + lr] = bb0.x; Bs[(kk + 1) * 132 + lr] = bb0.y;
        Bs[(kk + 2) * 132 + lr] = bb0.z; Bs[(kk + 3) * 132 + lr] = bb0.w;
        Bs[(kk + 4) * 132 + lr] = bb1.x; Bs[(kk + 5) * 132 + lr] = bb1.y;
        Bs[(kk + 6) * 132 + lr] = bb1.z; Bs[(kk + 7) * 132 + lr] = bb1.w;
        __syncthreads();

        if (ks < 11) {   // prefetch next k-tile (latency hidden by compute)
            int k0 = (ks + 1) * 16 + lq * 8;
            if (k0 < 64) {
                a0 = *reinterpret_cast<const float4*>(xrow + k0);
                a1 = *reinterpret_cast<const float4*>(xrow + k0 + 4);
            } else {
                a0 = *reinterpret_cast<const float4*>(hrow + k0 - 64);
                a1 = *reinterpret_cast<const float4*>(hrow + k0 - 60);
            }
            bb0 = *reinterpret_cast<const float4*>(brow + k0);
            bb1 = *reinterpret_cast<const float4*>(brow + k0 + 4);
        }

#pragma unroll
        for (int k2 = 0; k2 < 16; k2++) {
            ulonglong2 apl = *reinterpret_cast<const ulonglong2*>(&As[k2 * 132 + ty * 8]);
            ulonglong2 aph = *reinterpret_cast<const ulonglong2*>(&As[k2 * 132 + ty * 8 + 4]);
            float4 bv0 = *reinterpret_cast<const float4*>(&Bs[k2 * 132 + tx * 8]);
            float4 bv1 = *reinterpret_cast<const float4*>(&Bs[k2 * 132 + tx * 8 + 4]);
            u64 ap[4] = {apl.x, apl.y, aph.x, aph.y};
            u64 bs[8];
            bs[0] = splat2(bv0.x); bs[1] = splat2(bv0.y);
            bs[2] = splat2(bv0.z); bs[3] = splat2(bv0.w);
            bs[4] = splat2(bv1.x); bs[5] = splat2(bv1.y);
            bs[6] = splat2(bv1.z); bs[7] = splat2(bv1.w);
#pragma unroll
            for (int p = 0; p < 4; p++)
#pragma unroll
                for (int j = 0; j < 8; j++) fma2(acc[p][j], ap[p], bs[j]);
        }
        __syncthreads();
    }

    float bias[8];
#pragma unroll
    for (int j = 0; j < 8; j++) bias[j] = bih[n0 + tx * 8 + j];
#pragma unroll
    for (int p = 0; p < 4; p++) {
        float* orow0 = g_xp + (size_t)(m0 + ty * 8 + 2 * p) * G3 + n0 + tx * 8;
        float* orow1 = orow0 + G3;
#pragma unroll
        for (int j = 0; j < 8; j++) {
            float2 v = unpk2(acc[p][j]);
            orow0[j] = v.x + bias[j];
            orow1[j] = v.y + bias[j];
        }
    }
}

// ============================================================================
// K4: GRU scan. Persistent: 128 CTAs x 4 batch rows. 768 threads =
// 384 outputs x 2 k-halves; W_hh register-resident; f32x2 packed dot products;
// 2 barriers/step (halves write disjoint partial buffers).
// ============================================================================
__global__ __launch_bounds__(768, 1) void k4_gru(const float* __restrict__ whh,
                                                 const float* __restrict__ bhh) {
    __shared__ __align__(16) float hsh[4][HHD];
    __shared__ float gh0[4][G3];
    __shared__ float gh1[4][G3];
    __shared__ float xpsh[2][4][G3];

    int tid  = threadIdx.x;
    int half = (tid >= 384) ? 1 : 0;
    int j    = tid - half * 384;
    int b0   = blockIdx.x * 4;

    ulonglong2 w2[16];      // 64 w-floats packed as f32x2 pairs along k
    const ulonglong2* wp =
        reinterpret_cast<const ulonglong2*>(whh + (size_t)j * HHD + half * 64);
#pragma unroll
    for (int i = 0; i < 16; i++) w2[i] = wp[i];
    float bj = bhh[j];

    for (int i = tid; i < 4 * HHD; i += 768) hsh[i >> 7][i & 127] = 0.f;
    // preload xp for t = 0
    xpsh[0][half][j]     = g_xp[((size_t)(b0 + half) * TM) * G3 + j];
    xpsh[0][2 + half][j] = g_xp[((size_t)(b0 + 2 + half) * TM) * G3 + j];
    __syncthreads();

    const float* pfA = g_xp + ((size_t)(b0 + half) * TM + 1) * G3 + j;
    const float* pfB = g_xp + ((size_t)(b0 + 2 + half) * TM + 1) * G3 + j;

    int r0 = tid >> 7;       // update-phase mapping (tid < 512)
    int cc = tid & 127;
    float* gout = g_gru + ((size_t)(b0 + r0) * TM) * HHD + cc;

    for (int t = 0; t < TM; t++) {
        int cur = t & 1, nb = cur ^ 1;

        float pf0 = 0.f, pf1 = 0.f;
        if (t + 1 < TM) { pf0 = *pfA; pf1 = *pfB; }
        pfA += G3; pfB += G3;

        u64 a0 = 0ull, a1 = 0ull, a2 = 0ull, a3 = 0ull;
        const ulonglong2* h0 = reinterpret_cast<const ulonglong2*>(&hsh[0][half * 64]);
        const ulonglong2* h1 = reinterpret_cast<const ulonglong2*>(&hsh[1][half * 64]);
        const ulonglong2* h2 = reinterpret_cast<const ulonglong2*>(&hsh[2][half * 64]);
        const ulonglong2* h3 = reinterpret_cast<const ulonglong2*>(&hsh[3][half * 64]);
#pragma unroll
        for (int kq = 0; kq < 16; kq++) {
            ulonglong2 w = w2[kq];
            ulonglong2 v0 = h0[kq];
            fma2(a0, w.x, v0.x); fma2(a0, w.y, v0.y);
            ulonglong2 v1 = h1[kq];
            fma2(a1, w.x, v1.x); fma2(a1, w.y, v1.y);
            ulonglong2 v2 = h2[kq];
            fma2(a2, w.x, v2.x); fma2(a2, w.y, v2.y);
            ulonglong2 v3 = h3[kq];
            fma2(a3, w.x, v3.x); fma2(a3, w.y, v3.y);
        }
        float2 p0 = unpk2(a0), p1 = unpk2(a1), p2 = unpk2(a2), p3 = unpk2(a3);

        xpsh[nb][half][j]     = pf0;     // stash prefetch (read next step)
        xpsh[nb][2 + half][j] = pf1;
        if (half) {
            gh1[0][j] = p0.x + p0.y;
            gh1[1][j] = p1.x + p1.y;
            gh1[2][j] = p2.x + p2.y;
            gh1[3][j] = p3.x + p3.y;
        } else {
            gh0[0][j] = p0.x + p0.y + bj;
            gh0[1][j] = p1.x + p1.y + bj;
            gh0[2][j] = p2.x + p2.y + bj;
            gh0[3][j] = p3.x + p3.y + bj;
        }
        __syncthreads();

        if (tid < 512) {
            float xr = xpsh[cur][r0][cc];
            float xz = xpsh[cur][r0][cc + 128];
            float xn = xpsh[cur][r0][cc + 256];
            float hr = gh0[r0][cc]       + gh1[r0][cc];
            float hz = gh0[r0][cc + 128] + gh1[r0][cc + 128];
            float hn = gh0[r0][cc + 256] + gh1[r0][cc + 256];
            float rr = 1.f / (1.f + __expf(-(xr + hr)));
            float zg = 1.f / (1.f + __expf(-(xz + hz)));
            float nn = tanhf(xn + rr * hn);
            float hnew = (1.f - zg) * nn + zg * hsh[r0][cc];
            hsh[r0][cc] = hnew;
            *gout = hnew;
        }
        gout += HHD;
        __syncthreads();
    }
}

// ============================================================================
// K5: scores = relu(gru @ w1^T + b1) @ w2^T + b2.  Block: one b x 64 t's.
// f32x2 packed along k.
// ============================================================================
__global__ __launch_bounds__(256) void k5_scores(const float* __restrict__ w1,
                                                 const float* __restrict__ ab1,
                                                 const float* __restrict__ w2,
                                                 const float* __restrict__ ab2) {
    __shared__ __align__(16) float gsh[64 * 132];   // gru tile [tl*132 + k]
    __shared__ float wred[8][16];                   // per-warp partial scores
    int b   = blockIdx.y;
    int t0  = blockIdx.x * 64;
    int tid = threadIdx.x;

    for (int i = tid; i < 64 * 128; i += 256) {
        int tl = i >> 7, k = i & 127;
        int t = t0 + tl;
        gsh[tl * 132 + k] = (t < TM) ? g_gru[((size_t)b * TM + t) * HHD + k] : 0.f;
    }
    __syncthreads();

    int n  = tid & 63;
    int tg = tid >> 6;                  // 4 groups x 16 t's
    float bn  = ab1[n];
    float w2n = w2[n];

    u64 hid[16];
#pragma unroll
    for (int i = 0; i < 16; i++) hid[i] = 0ull;

    const float* wrow = w1 + (size_t)n * HHD;
#pragma unroll 8
    for (int k4 = 0; k4 < 32; k4++) {
        ulonglong2 wv = *reinterpret_cast<const ulonglong2*>(wrow + k4 * 4);
#pragma unroll
        for (int i = 0; i < 16; i++) {
            ulonglong2 gv =
                *reinterpret_cast<const ulonglong2*>(&gsh[(tg * 16 + i) * 132 + k4 * 4]);
            fma2(hid[i], wv.x, gv.x);
            fma2(hid[i], wv.y, gv.y);
        }
    }

    // per-thread contribution, warp-reduce over the 32 n-lanes of this warp
    int wid = tid >> 5;
#pragma unroll
    for (int i = 0; i < 16; i++) {
        float2 hp = unpk2(hid[i]);
        float sv = fmaxf(hp.x + hp.y + bn, 0.f) * w2n;
#pragma unroll
        for (int o = 16; o; o >>= 1) sv += __shfl_xor_sync(0xffffffffu, sv, o);
        if ((tid & 31) == 0) wred[wid][i] = sv;
    }
    __syncthreads();

    if (tid < 64) {                      // t_local = tid; warps 2*tg, 2*tg+1
        int tgg = tid >> 4, ii = tid & 15;
        float s = wred[2 * tgg][ii] + wred[2 * tgg + 1][ii] + ab2[0];
        int t = t0 + tid;
        if (t < TM) g_sc[(size_t)b * TM + t] = s;
    }
}

// ============================================================================
// K6: softmax over t, weighted pool of gru_out, fused head. One block per b.
// ============================================================================
__global__ __launch_bounds__(128) void k6_pool(const float* __restrict__ hw,
                                               const float* __restrict__ hb,
                                               float* __restrict__ out) {
    __shared__ float psh[TM];
    __shared__ float red[16];
    __shared__ float hann[HHD];
    int b   = blockIdx.x;
    int tid = threadIdx.x;
    const float* sc = g_sc + (size_t)b * TM;

    float mx = -1e30f;
    for (int t = tid; t < TM; t += 128) mx = fmaxf(mx, sc[t]);
#pragma unroll
    for (int o = 16; o; o >>= 1) mx = fmaxf(mx, __shfl_xor_sync(0xffffffffu, mx, o));
    if ((tid & 31) == 0) red[tid >> 5] = mx;
    __syncthreads();
    mx = fmaxf(fmaxf(red[0], red[1]), fmaxf(red[2], red[3]));

    float sm = 0.f;
    for (int t = tid; t < TM; t += 128) {
        float e = __expf(sc[t] - mx);
        psh[t] = e;
        sm += e;
    }
#pragma unroll
    for (int o = 16; o; o >>= 1) sm += __shfl_xor_sync(0xffffffffu, sm, o);
    if ((tid & 31) == 0) red[8 + (tid >> 5)] = sm;
    __syncthreads();
    sm = red[8] + red[9] + red[10] + red[11];
    float inv = 1.f / sm;

    const float* gb = g_gru + (size_t)b * TM * HHD + tid;   // tid == channel
    float acc = 0.f;
    int t = 0;
    for (; t + 4 <= TM; t += 4) {
        float g0 = gb[(size_t)(t + 0) * HHD];
        float g1 = gb[(size_t)(t + 1) * HHD];
        float g2 = gb[(size_t)(t + 2) * HHD];
        float g3 = gb[(size_t)(t + 3) * HHD];
        acc += psh[t] * g0 + psh[t + 1] * g1 + psh[t + 2] * g2 + psh[t + 3] * g3;
    }
    for (; t < TM; t++) acc += psh[t] * gb[(size_t)t * HHD];
    hann[tid] = acc * inv;
    __syncthreads();

    if (tid < HOR) {
        float s = hb[tid];
        const float* wr = hw + tid * HHD;
#pragma unroll 4
        for (int c = 0; c < HHD; c++) s += hann[c] * wr[c];
        out[b * HOR + tid] = s;
    }
}

// ============================================================================
extern "C" void kernel_launch(void* const* d_in, const int* in_sizes, int n_in,
                              void* d_out, int out_size) {
    const float* x       = (const float*)d_in[0];
    const float* proj_w  = (const float*)d_in[1];
    const float* proj_b  = (const float*)d_in[2];
    const float* beta1   = (const float*)d_in[3];
    const float* beta2   = (const float*)d_in[4];
    const float* gw_ih   = (const float*)d_in[5];
    const float* gw_hh   = (const float*)d_in[6];
    const float* gb_ih   = (const float*)d_in[7];
    const float* gb_hh   = (const float*)d_in[8];
    const float* attn_w1 = (const float*)d_in[9];
    const float* attn_b1 = (const float*)d_in[10];
    const float* attn_w2 = (const float*)d_in[11];
    const float* attn_b2 = (const float*)d_in[12];
    const float* head_w  = (const float*)d_in[13];
    const float* head_b  = (const float*)d_in[14];
    float* out = (float*)d_out;

    dim3 g1(32, BB);
    k1_hs<<<g1, 256>>>(x, proj_w, proj_b);
    k2_snn<<<BB, 128>>>(beta1, beta2);
    dim3 g3(3, 4092);                       // 384/128 n-tiles x 523776/128 m-tiles
    k3_xproj<<<g3, 256>>>(x, gw_ih, gb_ih);
    k4_gru<<<128, 768>>>(gw_hh, gb_hh);
    dim3 g5(16, BB);                        // ceil(1023/64) t-tiles x B
    k5_scores<<<g5, 256>>>(attn_w1, attn_b1, attn_w2, attn_b2);
    k6_pool<<<BB, 128>>>(head_w, head_b, out);
}

// round 17
// speedup vs baseline: 1.2712x; 1.2671x over previous
#include <cuda_runtime.h>
#include <math.h>

#define BB  512
#define TT  1024
#define TM  1023
#define FF  64
#define SN  128
#define HHD 128
#define G3  384
#define KC  192
#define HOR 24

typedef unsigned int uint32;

// ---------------- scratch (device globals; allocation-free) ----------------
__device__ float g_hs [(size_t)BB * TM * SN];   // h_s, overwritten in-place -> h_snn
__device__ float g_xp [(size_t)BB * TM * G3];   // x_proj
__device__ float g_gru[(size_t)BB * TM * HHD];  // gru_out
__device__ float g_sc [(size_t)BB * TM];        // attention scores

// ---------------- bf16 split helpers ----------------
// Split (x0, x1) into packed bf16x2 hi and lo: x = hi + lo (hi: bf16 RN of x,
// lo: bf16 RN of exact residual). Low 16 bits of the b32 hold element x0.
__device__ __forceinline__ void split2(float x0, float x1, uint32& hp, uint32& lp) {
    uint32 h;
    asm("cvt.rn.bf16x2.f32 %0,%1,%2;" : "=r"(h) : "f"(x1), "f"(x0));
    float h0 = __uint_as_float(h << 16);
    float h1 = __uint_as_float(h & 0xffff0000u);
    float l0 = x0 - h0;
    float l1 = x1 - h1;
    uint32 l;
    asm("cvt.rn.bf16x2.f32 %0,%1,%2;" : "=r"(l) : "f"(l1), "f"(l0));
    hp = h; lp = l;
}

__device__ __forceinline__ void mma_bf16(float* d,
                                         uint32 a0, uint32 a1, uint32 a2, uint32 a3,
                                         uint32 b0, uint32 b1) {
    asm volatile(
        "mma.sync.aligned.m16n8k16.row.col.f32.bf16.bf16.f32 "
        "{%0,%1,%2,%3},{%4,%5,%6,%7},{%8,%9},{%0,%1,%2,%3};"
        : "+f"(d[0]), "+f"(d[1]), "+f"(d[2]), "+f"(d[3])
        : "r"(a0), "r"(a1), "r"(a2), "r"(a3), "r"(b0), "r"(b1));
}

// ============================================================================
// K1: h_s[b,t,c] = sum_f (x[b,t+1,f]-x[b,t,f]) * proj_w[c,f] + proj_b[c]
// (pure fp32 — feeds the discontinuous SNN threshold)
// ============================================================================
__global__ __launch_bounds__(256) void k1_hs(const float* __restrict__ x,
                                             const float* __restrict__ pw,
                                             const float* __restrict__ pb) {
    __shared__ float wsh[FF * 129];   // [f*129 + c]  transposed proj_w
    __shared__ float dsh[32 * 68];    // [row*68 + f] delta tile
    int b   = blockIdx.y;
    int t0  = blockIdx.x * 32;
    int tid = threadIdx.x;

    for (int i = tid; i < SN * FF; i += 256) {
        int c = i >> 6, f = i & 63;
        wsh[f * 129 + c] = pw[i];
    }
    for (int i = tid; i < 32 * FF; i += 256) {
        int row = i >> 6, f = i & 63;
        int t = t0 + row;
        float d = 0.f;
        if (t < TM) {
            const float* xb = x + ((size_t)b * TT + t) * FF + f;
            d = xb[FF] - xb[0];
        }
        dsh[row * 68 + f] = d;
    }
    __syncthreads();

    int c  = tid & 127;
    int rg = tid >> 7;            // 0..1 -> 16 t's each
    float bias = pb[c];
    float acc[16];
#pragma unroll
    for (int i = 0; i < 16; i++) acc[i] = bias;

#pragma unroll
    for (int f4 = 0; f4 < FF; f4 += 4) {
        float w0 = wsh[(f4 + 0) * 129 + c];
        float w1 = wsh[(f4 + 1) * 129 + c];
        float w2 = wsh[(f4 + 2) * 129 + c];
        float w3 = wsh[(f4 + 3) * 129 + c];
#pragma unroll
        for (int i = 0; i < 16; i++) {
            float4 d4 = *reinterpret_cast<const float4*>(&dsh[(rg * 16 + i) * 68 + f4]);
            acc[i] += w0 * d4.x + w1 * d4.y + w2 * d4.z + w3 * d4.w;
        }
    }
#pragma unroll
    for (int i = 0; i < 16; i++) {
        int t = t0 + rg * 16 + i;
        if (t < TM) g_hs[((size_t)b * TM + t) * SN + c] = acc[i];
    }
}

// ============================================================================
// K2: LIF SNN scan, in-place on g_hs. One thread per (b, channel) chain.
// ============================================================================
__global__ __launch_bounds__(128) void k2_snn(const float* __restrict__ be1,
                                              const float* __restrict__ be2) {
    int c = threadIdx.x;
    int b = blockIdx.x;
    float bt1 = fminf(fmaxf(be1[c], 0.f), 0.99f);
    float bt2 = fminf(fmaxf(be2[c], 0.f), 0.99f);
    float m1 = 0.f, s1 = 0.f, m2 = 0.f, s2 = 0.f;
    float* p = g_hs + (size_t)b * TM * SN + c;

    int t = 0;
    for (; t + 4 <= TM; t += 4) {
        float i0 = p[0], i1 = p[SN], i2 = p[2 * SN], i3 = p[3 * SN];
        m1 = bt1 * m1 + i0 - s1; s1 = (m1 > 1.f) ? 1.f : 0.f;
        m2 = bt2 * m2 + s1 - s2; s2 = (m2 > 1.f) ? 1.f : 0.f;
        p[0] = m2;
        m1 = bt1 * m1 + i1 - s1; s1 = (m1 > 1.f) ? 1.f : 0.f;
        m2 = bt2 * m2 + s1 - s2; s2 = (m2 > 1.f) ? 1.f : 0.f;
        p[SN] = m2;
        m1 = bt1 * m1 + i2 - s1; s1 = (m1 > 1.f) ? 1.f : 0.f;
        m2 = bt2 * m2 + s1 - s2; s2 = (m2 > 1.f) ? 1.f : 0.f;
        p[2 * SN] = m2;
        m1 = bt1 * m1 + i3 - s1; s1 = (m1 > 1.f) ? 1.f : 0.f;
        m2 = bt2 * m2 + s1 - s2; s2 = (m2 > 1.f) ? 1.f : 0.f;
        p[3 * SN] = m2;
        p += 4 * SN;
    }
    for (; t < TM; t++) {
        float iv = p[0];
        m1 = bt1 * m1 + iv - s1; s1 = (m1 > 1.f) ? 1.f : 0.f;
        m2 = bt2 * m2 + s1 - s2; s2 = (m2 > 1.f) ? 1.f : 0.f;
        p[0] = m2;
        p += SN;
    }
}

// ============================================================================
// K3: x_proj = [raw | h_snn] @ W_ih^T + b_ih.  M=523776, N=384, K=192.
// TENSOR CORES: bf16 split-precision (hi/lo), 3x mma.sync.m16n8k16, fp32 accum.
// CTA tile 128x128, 8 warps (2x4), warp tile 64x32, 12 k16 steps.
// ============================================================================
__global__ __launch_bounds__(256) void k3_xproj(const float* __restrict__ x,
                                                const float* __restrict__ wih,
                                                const float* __restrict__ bih) {
    __shared__ __align__(16) unsigned short Ah[128 * 16];
    __shared__ __align__(16) unsigned short Al[128 * 16];
    __shared__ __align__(16) unsigned short Bh[128 * 16];
    __shared__ __align__(16) unsigned short Bl[128 * 16];

    int m0  = blockIdx.y * 128;
    int n0  = blockIdx.x * 128;
    int tid = threadIdx.x;
    int lr  = tid >> 1;     // 0..127: row (A) / col (B) for staging loads
    int lq  = tid & 1;      // k-half (8 floats)

    int m  = m0 + lr;
    int bb = m / TM;
    int tt = m - bb * TM;
    const float* xrow = x + ((size_t)bb * TT + tt + 1) * FF;   // raw, k < 64
    const float* hrow = g_hs + (size_t)m * SN;                 // h_snn, k >= 64
    const float* brow = wih + (size_t)(n0 + lr) * KC;

    int lane = tid & 31;
    int wid  = tid >> 5;
    int gid  = lane >> 2;     // 0..7
    int tig  = lane & 3;      // 0..3
    int wm   = (wid >> 2) * 64;   // warp m-offset: 0 / 64
    int wn   = (wid & 3) * 32;    // warp n-offset: 0 / 32 / 64 / 96

    float d[4][4][4];
#pragma unroll
    for (int i = 0; i < 4; i++)
#pragma unroll
        for (int j = 0; j < 4; j++)
#pragma unroll
            for (int q = 0; q < 4; q++) d[i][j][q] = 0.f;

    float4 a0, a1, bv0, bv1;
    {   // prologue: ks = 0 (k0 < 64 always -> from xrow)
        int k0 = lq * 8;
        a0  = *reinterpret_cast<const float4*>(xrow + k0);
        a1  = *reinterpret_cast<const float4*>(xrow + k0 + 4);
        bv0 = *reinterpret_cast<const float4*>(brow + k0);
        bv1 = *reinterpret_cast<const float4*>(brow + k0 + 4);
    }

    int sidx = lr * 16 + lq * 8;   // element index into 128x16 tiles

    for (int ks = 0; ks < 12; ks++) {
        // ---- split staged fp32 regs into bf16 hi/lo tiles ----
        {
            uint32 h0, h1, h2, h3, l0, l1, l2, l3;
            split2(a0.x, a0.y, h0, l0);
            split2(a0.z, a0.w, h1, l1);
            split2(a1.x, a1.y, h2, l2);
            split2(a1.z, a1.w, h3, l3);
            *reinterpret_cast<uint4*>(&Ah[sidx]) = make_uint4(h0, h1, h2, h3);
            *reinterpret_cast<uint4*>(&Al[sidx]) = make_uint4(l0, l1, l2, l3);
            split2(bv0.x, bv0.y, h0, l0);
            split2(bv0.z, bv0.w, h1, l1);
            split2(bv1.x, bv1.y, h2, l2);
            split2(bv1.z, bv1.w, h3, l3);
            *reinterpret_cast<uint4*>(&Bh[sidx]) = make_uint4(h0, h1, h2, h3);
            *reinterpret_cast<uint4*>(&Bl[sidx]) = make_uint4(l0, l1, l2, l3);
        }
        __syncthreads();

        if (ks < 11) {   // prefetch next k16 tile
            int k0 = (ks + 1) * 16 + lq * 8;
            if (k0 < 64) {
                a0 = *reinterpret_cast<const float4*>(xrow + k0);
                a1 = *reinterpret_cast<const float4*>(xrow + k0 + 4);
            } else {
                a0 = *reinterpret_cast<const float4*>(hrow + k0 - 64);
                a1 = *reinterpret_cast<const float4*>(hrow + k0 - 60);
            }
            bv0 = *reinterpret_cast<const float4*>(brow + k0);
            bv1 = *reinterpret_cast<const float4*>(brow + k0 + 4);
        }

        // ---- B fragments (k x n col-major view): b0 k=2tig..+1, b1 k=+8 ----
        uint32 fbh[4][2], fbl[4][2];
#pragma unroll
        for (int nt = 0; nt < 4; nt++) {
            int n = wn + nt * 8 + gid;
            fbh[nt][0] = *reinterpret_cast<const uint32*>(&Bh[n * 16 + 2 * tig]);
            fbh[nt][1] = *reinterpret_cast<const uint32*>(&Bh[n * 16 + 2 * tig + 8]);
            fbl[nt][0] = *reinterpret_cast<const uint32*>(&Bl[n * 16 + 2 * tig]);
            fbl[nt][1] = *reinterpret_cast<const uint32*>(&Bl[n * 16 + 2 * tig + 8]);
        }

#pragma unroll
        for (int mt = 0; mt < 4; mt++) {
            int r = wm + mt * 16 + gid;
            uint32 ah0 = *reinterpret_cast<const uint32*>(&Ah[r * 16 + 2 * tig]);
            uint32 ah1 = *reinterpret_cast<const uint32*>(&Ah[(r + 8) * 16 + 2 * tig]);
            uint32 ah2 = *reinterpret_cast<const uint32*>(&Ah[r * 16 + 2 * tig + 8]);
            uint32 ah3 = *reinterpret_cast<const uint32*>(&Ah[(r + 8) * 16 + 2 * tig + 8]);
            uint32 al0 = *reinterpret_cast<const uint32*>(&Al[r * 16 + 2 * tig]);
            uint32 al1 = *reinterpret_cast<const uint32*>(&Al[(r + 8) * 16 + 2 * tig]);
            uint32 al2 = *reinterpret_cast<const uint32*>(&Al[r * 16 + 2 * tig + 8]);
            uint32 al3 = *reinterpret_cast<const uint32*>(&Al[(r + 8) * 16 + 2 * tig + 8]);
#pragma unroll
            for (int nt = 0; nt < 4; nt++) {
                mma_bf16(d[mt][nt], ah0, ah1, ah2, ah3, fbh[nt][0], fbh[nt][1]);
                mma_bf16(d[mt][nt], ah0, ah1, ah2, ah3, fbl[nt][0], fbl[nt][1]);
                mma_bf16(d[mt][nt], al0, al1, al2, al3, fbh[nt][0], fbh[nt][1]);
            }
        }
        __syncthreads();
    }

    // ---- epilogue: c0/c1 at (gid, 2tig/2tig+1), c2/c3 at row+8 ----
#pragma unroll
    for (int nt = 0; nt < 4; nt++) {
        int col = n0 + wn + nt * 8 + 2 * tig;
        float e0 = bih[col], e1 = bih[col + 1];
#pragma unroll
        for (int mt = 0; mt < 4; mt++) {
            int row = m0 + wm + mt * 16 + gid;
            float2 v0 = make_float2(d[mt][nt][0] + e0, d[mt][nt][1] + e1);
            float2 v1 = make_float2(d[mt][nt][2] + e0, d[mt][nt][3] + e1);
            *reinterpret_cast<float2*>(&g_xp[(size_t)row * G3 + col]) = v0;
            *reinterpret_cast<float2*>(&g_xp[(size_t)(row + 8) * G3 + col]) = v1;
        }
    }
}

// ============================================================================
// K4: GRU scan. Persistent: 128 CTAs x 4 batch rows. 768 threads =
// 384 outputs x 2 k-halves; W_hh rows live in registers (64 f32/thread).
// (reverted to the known-good FFMA version)
// ============================================================================
__global__ __launch_bounds__(768, 1) void k4_gru(const float* __restrict__ whh,
                                                 const float* __restrict__ bhh) {
    __shared__ float hsh[4][HHD];
    __shared__ float ghsh[4][G3];
    __shared__ float xpsh[2][4][G3];

    int tid  = threadIdx.x;
    int half = (tid >= 384) ? 1 : 0;
    int j    = tid - half * 384;
    int b0   = blockIdx.x * 4;

    float4 w4[16];
    const float4* wp = reinterpret_cast<const float4*>(whh + (size_t)j * HHD + half * 64);
#pragma unroll
    for (int i = 0; i < 16; i++) w4[i] = wp[i];
    float bj = bhh[j];

    for (int i = tid; i < 4 * HHD; i += 768) hsh[i >> 7][i & 127] = 0.f;
    // preload xp for t = 0
    xpsh[0][half][j]     = g_xp[((size_t)(b0 + half) * TM) * G3 + j];
    xpsh[0][2 + half][j] = g_xp[((size_t)(b0 + 2 + half) * TM) * G3 + j];
    __syncthreads();

    int r0 = tid >> 7;       // update-phase mapping (tid < 512)
    int cc = tid & 127;

    for (int t = 0; t < TM; t++) {
        int cur = t & 1, nb = cur ^ 1;

        float pf0 = 0.f, pf1 = 0.f;
        if (t + 1 < TM) {
            pf0 = g_xp[((size_t)(b0 + half) * TM + t + 1) * G3 + j];
            pf1 = g_xp[((size_t)(b0 + 2 + half) * TM + t + 1) * G3 + j];
        }

        float a0 = 0.f, a1 = 0.f, a2 = 0.f, a3 = 0.f;
        const float* h0 = &hsh[0][half * 64];
        const float* h1 = &hsh[1][half * 64];
        const float* h2 = &hsh[2][half * 64];
        const float* h3 = &hsh[3][half * 64];
#pragma unroll
        for (int kq = 0; kq < 16; kq++) {
            float4 w = w4[kq];
            float4 v0 = *reinterpret_cast<const float4*>(h0 + kq * 4);
            a0 += w.x * v0.x + w.y * v0.y + w.z * v0.z + w.w * v0.w;
            float4 v1 = *reinterpret_cast<const float4*>(h1 + kq * 4);
            a1 += w.x * v1.x + w.y * v1.y + w.z * v1.z + w.w * v1.w;
            float4 v2 = *reinterpret_cast<const float4*>(h2 + kq * 4);
            a2 += w.x * v2.x + w.y * v2.y + w.z * v2.z + w.w * v2.w;
            float4 v3 = *reinterpret_cast<const float4*>(h3 + kq * 4);
            a3 += w.x * v3.x + w.y * v3.y + w.z * v3.z + w.w * v3.w;
        }

        xpsh[nb][half][j]     = pf0;     // stash prefetch (read next step)
        xpsh[nb][2 + half][j] = pf1;
        if (half == 1) {
            ghsh[0][j] = a0; ghsh[1][j] = a1; ghsh[2][j] = a2; ghsh[3][j] = a3;
        }
        __syncthreads();
        if (half == 0) {
            ghsh[0][j] = a0 + ghsh[0][j] + bj;
            ghsh[1][j] = a1 + ghsh[1][j] + bj;
            ghsh[2][j] = a2 + ghsh[2][j] + bj;
            ghsh[3][j] = a3 + ghsh[3][j] + bj;
        }
        __syncthreads();

        if (tid < 512) {
            float xr = xpsh[cur][r0][cc];
            float xz = xpsh[cur][r0][cc + 128];
            float xn = xpsh[cur][r0][cc + 256];
            float hr = ghsh[r0][cc];
            float hz = ghsh[r0][cc + 128];
            float hn = ghsh[r0][cc + 256];
            float rr = 1.f / (1.f + __expf(-(xr + hr)));
            float zg = 1.f / (1.f + __expf(-(xz + hz)));
            float nn = tanhf(xn + rr * hn);
            float hold = hsh[r0][cc];
            float hnew = (1.f - zg) * nn + zg * hold;
            hsh[r0][cc] = hnew;
            g_gru[((size_t)(b0 + r0) * TM + t) * HHD + cc] = hnew;
        }
        __syncthreads();
    }
}

// ============================================================================
// K5: scores = relu(gru @ w1^T + b1) @ w2^T + b2.  Block: one b x 64 t's.
// ============================================================================
__global__ __launch_bounds__(256) void k5_scores(const float* __restrict__ w1,
                                                 const float* __restrict__ ab1,
                                                 const float* __restrict__ w2,
                                                 const float* __restrict__ ab2) {
    __shared__ float gsh[64 * 132];   // gru tile [tl*132 + k]
    __shared__ float wred[8][16];     // per-warp partial scores
    int b   = blockIdx.y;
    int t0  = blockIdx.x * 64;
    int tid = threadIdx.x;

    for (int i = tid; i < 64 * 128; i += 256) {
        int tl = i >> 7, k = i & 127;
        int t = t0 + tl;
        gsh[tl * 132 + k] = (t < TM) ? g_gru[((size_t)b * TM + t) * HHD + k] : 0.f;
    }
    __syncthreads();

    int n  = tid & 63;
    int tg = tid >> 6;                  // 4 groups x 16 t's
    float bn  = ab1[n];
    float w2n = w2[n];

    float hid[16];
#pragma unroll
    for (int i = 0; i < 16; i++) hid[i] = bn;

    const float* wrow = w1 + (size_t)n * HHD;
#pragma unroll 8
    for (int k4 = 0; k4 < 32; k4++) {
        float4 wv = *reinterpret_cast<const float4*>(wrow + k4 * 4);
#pragma unroll
        for (int i = 0; i < 16; i++) {
            float4 gv = *reinterpret_cast<const float4*>(&gsh[(tg * 16 + i) * 132 + k4 * 4]);
            hid[i] += wv.x * gv.x + wv.y * gv.y + wv.z * gv.z + wv.w * gv.w;
        }
    }

    int wid = tid >> 5;
#pragma unroll
    for (int i = 0; i < 16; i++) {
        float sv = fmaxf(hid[i], 0.f) * w2n;
#pragma unroll
        for (int o = 16; o; o >>= 1) sv += __shfl_xor_sync(0xffffffffu, sv, o);
        if ((tid & 31) == 0) wred[wid][i] = sv;
    }
    __syncthreads();

    if (tid < 64) {                      // t_local = tid; warps 2*tg, 2*tg+1
        int tgg = tid >> 4, ii = tid & 15;
        float s = wred[2 * tgg][ii] + wred[2 * tgg + 1][ii] + ab2[0];
        int t = t0 + tid;
        if (t < TM) g_sc[(size_t)b * TM + t] = s;
    }
}

// ============================================================================
// K6: softmax over t, weighted pool of gru_out, fused head. One block per b.
// ============================================================================
__global__ __launch_bounds__(128) void k6_pool(const float* __restrict__ hw,
                                               const float* __restrict__ hb,
                                               float* __restrict__ out) {
    __shared__ float psh[TM];
    __shared__ float red[16];
    __shared__ float hann[HHD];
    int b   = blockIdx.x;
    int tid = threadIdx.x;
    const float* sc = g_sc + (size_t)b * TM;

    float mx = -1e30f;
    for (int t = tid; t < TM; t += 128) mx = fmaxf(mx, sc[t]);
#pragma unroll
    for (int o = 16; o; o >>= 1) mx = fmaxf(mx, __shfl_xor_sync(0xffffffffu, mx, o));
    if ((tid & 31) == 0) red[tid >> 5] = mx;
    __syncthreads();
    mx = fmaxf(fmaxf(red[0], red[1]), fmaxf(red[2], red[3]));

    float sm = 0.f;
    for (int t = tid; t < TM; t += 128) {
        float e = __expf(sc[t] - mx);
        psh[t] = e;
        sm += e;
    }
#pragma unroll
    for (int o = 16; o; o >>= 1) sm += __shfl_xor_sync(0xffffffffu, sm, o);
    if ((tid & 31) == 0) red[8 + (tid >> 5)] = sm;
    __syncthreads();
    sm = red[8] + red[9] + red[10] + red[11];
    float inv = 1.f / sm;

    const float* gb = g_gru + (size_t)b * TM * HHD + tid;   // tid == channel
    float acc = 0.f;
    int t = 0;
    for (; t + 4 <= TM; t += 4) {
        float g0 = gb[(size_t)(t + 0) * HHD];
        float g1 = gb[(size_t)(t + 1) * HHD];
        float g2 = gb[(size_t)(t + 2) * HHD];
        float g3 = gb[(size_t)(t + 3) * HHD];
        acc += psh[t] * g0 + psh[t + 1] * g1 + psh[t + 2] * g2 + psh[t + 3] * g3;
    }
    for (; t < TM; t++) acc += psh[t] * gb[(size_t)t * HHD];
    hann[tid] = acc * inv;
    __syncthreads();

    if (tid < HOR) {
        float s = hb[tid];
        const float* wr = hw + tid * HHD;
#pragma unroll 4
        for (int c = 0; c < HHD; c++) s += hann[c] * wr[c];
        out[b * HOR + tid] = s;
    }
}

// ============================================================================
extern "C" void kernel_launch(void* const* d_in, const int* in_sizes, int n_in,
                              void* d_out, int out_size) {
    const float* x       = (const float*)d_in[0];
    const float* proj_w  = (const float*)d_in[1];
    const float* proj_b  = (const float*)d_in[2];
    const float* beta1   = (const float*)d_in[3];
    const float* beta2   = (const float*)d_in[4];
    const float* gw_ih   = (const float*)d_in[5];
    const float* gw_hh   = (const float*)d_in[6];
    const float* gb_ih   = (const float*)d_in[7];
    const float* gb_hh   = (const float*)d_in[8];
    const float* attn_w1 = (const float*)d_in[9];
    const float* attn_b1 = (const float*)d_in[10];
    const float* attn_w2 = (const float*)d_in[11];
    const float* attn_b2 = (const float*)d_in[12];
    const float* head_w  = (const float*)d_in[13];
    const float* head_b  = (const float*)d_in[14];
    float* out = (float*)d_out;

    dim3 g1(32, BB);
    k1_hs<<<g1, 256>>>(x, proj_w, proj_b);
    k2_snn<<<BB, 128>>>(beta1, beta2);
    dim3 g3(3, 4092);                       // 384/128 n-tiles x 523776/128 m-tiles
    k3_xproj<<<g3, 256>>>(x, gw_ih, gb_ih);
    k4_gru<<<128, 768>>>(gw_hh, gb_hh);
    dim3 g5(16, BB);                        // ceil(1023/64) t-tiles x B
    k5_scores<<<g5, 256>>>(attn_w1, attn_b1, attn_w2, attn_b2);
    k6_pool<<<BB, 128>>>(head_w, head_b, out);
}